// round 8
// baseline (speedup 1.0000x reference)
#include <cuda_runtime.h>
#include <cstdint>
#include <cstddef>

// TensorFusion: B=32, N=4096, C=16, D=256
//   out[b,c,d]  = (1/N) * sum_n [r[b,n,c] >= 0.5] * v[b,n,d]        c in 0..15
//   out[b,16,d] = (1/N) * sum_n [all c: r[b,n,c] < 0.5] * v[b,n,d]

#define B_DIM 32
#define N_DIM 4096
#define C_DIM 16
#define D_DIM 256
#define OUT_C (C_DIM + 1)

#define SPLIT 16
#define NCHUNK (N_DIM / SPLIT)     // 256 rows per CTA
#define THREADS 256
#define NGROUPS 4
#define RPG (NCHUNK / NGROUPS)     // 64 rows per n-group

__global__ void tf_zero_kernel(float* __restrict__ out, int n) {
    int i = blockIdx.x * blockDim.x + threadIdx.x;
    if (i < n) out[i] = 0.0f;
}

// Predicated packed-f32x2 accumulate: if (mbit != 0) { a0 += v.x; a1 += v.y; }
// One setp guards two FADD2s (4 fp32 adds in ~3 issue slots + 1 predicate op).
__device__ __forceinline__ void acc_row(unsigned mbit, ulonglong2 vv,
                                        unsigned long long& a0,
                                        unsigned long long& a1) {
    asm("{\n\t"
        ".reg .pred p;\n\t"
        "setp.ne.u32 p, %4, 0;\n\t"
        "@p add.rn.f32x2 %0, %0, %2;\n\t"
        "@p add.rn.f32x2 %1, %1, %3;\n\t"
        "}"
        : "+l"(a0), "+l"(a1)
        : "l"(vv.x), "l"(vv.y), "r"(mbit));
}

__global__ __launch_bounds__(THREADS, 2)
void tf_fusion_kernel(const float* __restrict__ r,
                      const float* __restrict__ v,
                      float* __restrict__ out) {
    __shared__ __align__(16) unsigned smem_mask[NCHUNK];
    __shared__ __align__(16) float red[OUT_C][D_DIM];   // 17.4 KB

    const int b  = blockIdx.y;
    const int n0 = blockIdx.x * NCHUNK;
    const int t  = threadIdx.x;
    const int g  = t >> 6;        // n-group 0..3
    const int q  = t & 63;        // d-quad index (owns d = 4q..4q+3)

    // ---- Phase A: one 17-bit mask word per row of this chunk ----
    {
        const float4* rp = reinterpret_cast<const float4*>(
            r + (size_t)(b * N_DIM + n0 + t) * C_DIM);
        unsigned m = 0u;
        #pragma unroll
        for (int j = 0; j < 4; ++j) {
            float4 x = rp[j];
            m |= (x.x >= 0.5f ? 1u : 0u) << (4 * j + 0);
            m |= (x.y >= 0.5f ? 1u : 0u) << (4 * j + 1);
            m |= (x.z >= 0.5f ? 1u : 0u) << (4 * j + 2);
            m |= (x.w >= 0.5f ? 1u : 0u) << (4 * j + 3);
        }
        if (m == 0u) m = 1u << 16;   // special channel: no category matched
        smem_mask[t] = m;
    }
    __syncthreads();

    // ---- Phase B: group g streams its 64 rows; thread owns 4 d-columns ----
    // Accumulators: 17 channels x 4 floats, held as packed f32x2 pairs.
    unsigned long long a0[OUT_C], a1[OUT_C];
    #pragma unroll
    for (int c = 0; c < OUT_C; ++c) { a0[c] = 0ull; a1[c] = 0ull; }

    // v row = 256 floats = 1 KB = 64 x 16B; thread reads 16B at quad q.
    const ulonglong2* vp = reinterpret_cast<const ulonglong2*>(
        v + (size_t)(b * N_DIM + n0 + g * RPG) * D_DIM) + q;
    const unsigned* mrow = smem_mask + g * RPG;

    #pragma unroll 1
    for (int i = 0; i < RPG; i += 4) {
        // Batch 4 independent 16B global loads (MLP=4) + 1 LDS.128 for masks.
        ulonglong2 x0 = vp[(size_t)(i + 0) * (D_DIM / 4)];
        ulonglong2 x1 = vp[(size_t)(i + 1) * (D_DIM / 4)];
        ulonglong2 x2 = vp[(size_t)(i + 2) * (D_DIM / 4)];
        ulonglong2 x3 = vp[(size_t)(i + 3) * (D_DIM / 4)];
        uint4 mm = *reinterpret_cast<const uint4*>(mrow + i);
        #pragma unroll
        for (int c = 0; c < OUT_C; ++c) {
            const unsigned bit = 1u << c;
            acc_row(mm.x & bit, x0, a0[c], a1[c]);
            acc_row(mm.y & bit, x1, a0[c], a1[c]);
            acc_row(mm.z & bit, x2, a0[c], a1[c]);
            acc_row(mm.w & bit, x3, a0[c], a1[c]);
        }
    }
    __syncthreads();   // smem_mask no longer needed; red takes over

    // ---- Phase C1: reduce the 4 n-groups through shared memory ----
    #pragma unroll 1
    for (int gg = 0; gg < NGROUPS; ++gg) {
        if (g == gg) {
            #pragma unroll
            for (int c = 0; c < OUT_C; ++c) {
                float2 lo = *reinterpret_cast<float2*>(&a0[c]);
                float2 hi = *reinterpret_cast<float2*>(&a1[c]);
                float4* dst = reinterpret_cast<float4*>(&red[c][q * 4]);
                if (gg == 0) {
                    *dst = make_float4(lo.x, lo.y, hi.x, hi.y);
                } else {
                    float4 p = *dst;
                    *dst = make_float4(p.x + lo.x, p.y + lo.y,
                                       p.z + hi.x, p.w + hi.y);
                }
            }
        }
        __syncthreads();
    }

    // ---- Phase C2: scale + one atomic pass (256 threads cover D) ----
    const float scale = 1.0f / (float)N_DIM;
    float* op = out + (size_t)b * OUT_C * D_DIM + t;
    #pragma unroll
    for (int c = 0; c < OUT_C; ++c) {
        atomicAdd(op + c * D_DIM, red[c][t] * scale);
    }
}

extern "C" void kernel_launch(void* const* d_in, const int* in_sizes, int n_in,
                              void* d_out, int out_size) {
    // Inputs per metadata order: r_tensor (B*N*C), v_tensor (B*N*D).
    // Disambiguate defensively by element count.
    const float* r = (const float*)d_in[0];
    const float* v = (const float*)d_in[1];
    if (n_in >= 2 && in_sizes[0] == B_DIM * N_DIM * D_DIM &&
        in_sizes[1] == B_DIM * N_DIM * C_DIM) {
        r = (const float*)d_in[1];
        v = (const float*)d_in[0];
    }
    float* out = (float*)d_out;

    const int out_elems = B_DIM * OUT_C * D_DIM;  // 139264
    tf_zero_kernel<<<(out_elems + 255) / 256, 256>>>(out, out_elems);

    dim3 grid(SPLIT, B_DIM);
    tf_fusion_kernel<<<grid, THREADS>>>(r, v, out);
}